// round 1
// baseline (speedup 1.0000x reference)
#include <cuda_runtime.h>
#include <cuda_bf16.h>
#include <math.h>

// Problem constants
#define BB 8
#define NN 1024
#define DIM 512
#define HEADS 8
#define DHEAD 64
#define INNER 512           // HEADS*DHEAD
#define QKV_COLS 1536       // 3*INNER
#define MTOT (BB*NN)        // 8192

// ---------------------------------------------------------------------------
// Scratch (device globals; no allocation allowed)
// ---------------------------------------------------------------------------
__device__ float g_qkv[MTOT * QKV_COLS];   // 48 MB
__device__ float g_attn[MTOT * INNER];     // 16 MB

// ---------------------------------------------------------------------------
// SGEMM: C[M,N] = A[M,K] @ B[K,N] (+ bias[N] if bias != nullptr)
// BM=BN=128, BK=16, 256 threads, 8x8 per thread
// ---------------------------------------------------------------------------
#define GM_BM 128
#define GM_BN 128
#define GM_BK 16

__global__ __launch_bounds__(256, 2)
void sgemm_kernel(const float* __restrict__ A, const float* __restrict__ B,
                  const float* __restrict__ bias, float* __restrict__ C,
                  int M, int N, int K)
{
    __shared__ float As[GM_BK][GM_BM];
    __shared__ float Bs[GM_BK][GM_BN];

    const int tid  = threadIdx.x;
    const int row0 = blockIdx.y * GM_BM;
    const int col0 = blockIdx.x * GM_BN;
    const int tm   = tid >> 4;        // 0..15
    const int tn   = tid & 15;        // 0..15

    const int arow = tid >> 2;        // 0..63
    const int acol = (tid & 3) * 4;   // 0,4,8,12
    const int brow = tid >> 5;        // 0..7
    const int bcol = (tid & 31) * 4;  // 0..124

    float acc[8][8];
    #pragma unroll
    for (int i = 0; i < 8; ++i)
        #pragma unroll
        for (int j = 0; j < 8; ++j) acc[i][j] = 0.f;

    for (int k0 = 0; k0 < K; k0 += GM_BK) {
        // Load A tile (128x16), store transposed As[k][m]
        #pragma unroll
        for (int r = 0; r < 2; ++r) {
            int row = arow + r * 64;
            float4 a = *(const float4*)&A[(size_t)(row0 + row) * K + k0 + acol];
            As[acol + 0][row] = a.x;
            As[acol + 1][row] = a.y;
            As[acol + 2][row] = a.z;
            As[acol + 3][row] = a.w;
        }
        // Load B tile (16x128)
        #pragma unroll
        for (int r = 0; r < 2; ++r) {
            int rr = brow + r * 8;
            *(float4*)&Bs[rr][bcol] =
                *(const float4*)&B[(size_t)(k0 + rr) * N + col0 + bcol];
        }
        __syncthreads();

        #pragma unroll
        for (int k = 0; k < GM_BK; ++k) {
            float af[8], bf[8];
            *(float4*)&af[0] = *(const float4*)&As[k][tm * 8];
            *(float4*)&af[4] = *(const float4*)&As[k][tm * 8 + 4];
            *(float4*)&bf[0] = *(const float4*)&Bs[k][tn * 8];
            *(float4*)&bf[4] = *(const float4*)&Bs[k][tn * 8 + 4];
            #pragma unroll
            for (int i = 0; i < 8; ++i)
                #pragma unroll
                for (int j = 0; j < 8; ++j)
                    acc[i][j] = fmaf(af[i], bf[j], acc[i][j]);
        }
        __syncthreads();
    }

    // Epilogue (optionally add bias), vectorized stores
    float bvals[8];
    if (bias) {
        #pragma unroll
        for (int j = 0; j < 8; ++j) bvals[j] = bias[col0 + tn * 8 + j];
    } else {
        #pragma unroll
        for (int j = 0; j < 8; ++j) bvals[j] = 0.f;
    }
    #pragma unroll
    for (int i = 0; i < 8; ++i) {
        int row = row0 + tm * 8 + i;
        float4 v0, v1;
        v0.x = acc[i][0] + bvals[0]; v0.y = acc[i][1] + bvals[1];
        v0.z = acc[i][2] + bvals[2]; v0.w = acc[i][3] + bvals[3];
        v1.x = acc[i][4] + bvals[4]; v1.y = acc[i][5] + bvals[5];
        v1.z = acc[i][6] + bvals[6]; v1.w = acc[i][7] + bvals[7];
        *(float4*)&C[(size_t)row * N + col0 + tn * 8]     = v0;
        *(float4*)&C[(size_t)row * N + col0 + tn * 8 + 4] = v1;
    }
}

// ---------------------------------------------------------------------------
// Flash attention: one CTA per (b, h, 64-row Q tile). N=1024, d=64.
// Diagonal masked to -inf, online softmax, P staged through smem.
// ---------------------------------------------------------------------------
#define FB_BM 64
#define FB_BN 64
#define FB_D  64
#define FB_LD 65   // +1 pad

__global__ __launch_bounds__(256)
void flash_attn_kernel(const float* __restrict__ qkv,
                       const float* __restrict__ temperature,
                       float* __restrict__ out)
{
    extern __shared__ float sm[];
    float* Qs = sm;                      // [64][65]
    float* Ks = Qs + FB_BM * FB_LD;      // [64][65]
    float* Vs = Ks + FB_BN * FB_LD;      // [64][65]
    float* Ps = Vs + FB_BN * FB_LD;      // [64][65]

    const int tid = threadIdx.x;
    const int tx  = tid & 15;            // key-col group
    const int ty  = tid >> 4;            // query-row group
    const int r0  = ty * 4;
    const int c0  = tx * 4;

    const int qtile = blockIdx.x;        // 0..15
    const int h     = blockIdx.y;        // 0..7
    const int b     = blockIdx.z;        // 0..7
    const int q0    = qtile * FB_BM;

    const float scale = __expf(*temperature);

    const float* qbase = qkv + (size_t)b * NN * QKV_COLS + h * DHEAD;
    const float* kbase = qbase + INNER;
    const float* vbase = qbase + 2 * INNER;

    // Load Q tile (64x64)
    for (int idx = tid; idx < FB_BM * FB_D; idx += 256) {
        int m = idx >> 6, d = idx & 63;
        Qs[m * FB_LD + d] = qbase[(size_t)(q0 + m) * QKV_COLS + d];
    }

    float o[16];
    float mrow[4], lrow[4];
    #pragma unroll
    for (int i = 0; i < 16; ++i) o[i] = 0.f;
    #pragma unroll
    for (int i = 0; i < 4; ++i) { mrow[i] = -INFINITY; lrow[i] = 0.f; }

    for (int kt = 0; kt < NN / FB_BN; ++kt) {
        const int k0 = kt * FB_BN;
        __syncthreads();   // protect Ks/Vs (and Qs on first iter) from prior use
        for (int idx = tid; idx < FB_BN * FB_D; idx += 256) {
            int n = idx >> 6, d = idx & 63;
            Ks[n * FB_LD + d] = kbase[(size_t)(k0 + n) * QKV_COLS + d];
            Vs[n * FB_LD + d] = vbase[(size_t)(k0 + n) * QKV_COLS + d];
        }
        __syncthreads();

        // S = Q K^T (4x4 per thread)
        float s[16];
        #pragma unroll
        for (int i = 0; i < 16; ++i) s[i] = 0.f;
        #pragma unroll 8
        for (int d = 0; d < FB_D; ++d) {
            float qv[4], kv[4];
            #pragma unroll
            for (int i = 0; i < 4; ++i) qv[i] = Qs[(r0 + i) * FB_LD + d];
            #pragma unroll
            for (int j = 0; j < 4; ++j) kv[j] = Ks[(c0 + j) * FB_LD + d];
            #pragma unroll
            for (int i = 0; i < 4; ++i)
                #pragma unroll
                for (int j = 0; j < 4; ++j)
                    s[i * 4 + j] = fmaf(qv[i], kv[j], s[i * 4 + j]);
        }

        // scale + diagonal mask
        #pragma unroll
        for (int i = 0; i < 4; ++i) {
            int gi = q0 + r0 + i;
            #pragma unroll
            for (int j = 0; j < 4; ++j) {
                int gj = k0 + c0 + j;
                float v = s[i * 4 + j] * scale;
                s[i * 4 + j] = (gi == gj) ? -1e30f : v;
            }
        }

        // online softmax per row (reduce across the 16 tx lanes)
        #pragma unroll
        for (int i = 0; i < 4; ++i) {
            float mx = s[i * 4 + 0];
            mx = fmaxf(mx, s[i * 4 + 1]);
            mx = fmaxf(mx, s[i * 4 + 2]);
            mx = fmaxf(mx, s[i * 4 + 3]);
            #pragma unroll
            for (int off = 8; off >= 1; off >>= 1)
                mx = fmaxf(mx, __shfl_xor_sync(0xffffffffu, mx, off));
            float mnew  = fmaxf(mrow[i], mx);
            float alpha = __expf(mrow[i] - mnew);
            mrow[i] = mnew;

            float lsum = 0.f;
            #pragma unroll
            for (int j = 0; j < 4; ++j) {
                float p = __expf(s[i * 4 + j] - mnew);
                s[i * 4 + j] = p;
                lsum += p;
            }
            #pragma unroll
            for (int off = 8; off >= 1; off >>= 1)
                lsum += __shfl_xor_sync(0xffffffffu, lsum, off);
            lrow[i] = lrow[i] * alpha + lsum;
            #pragma unroll
            for (int j = 0; j < 4; ++j) o[i * 4 + j] *= alpha;
        }

        // stage P in smem
        #pragma unroll
        for (int i = 0; i < 4; ++i)
            #pragma unroll
            for (int j = 0; j < 4; ++j)
                Ps[(r0 + i) * FB_LD + c0 + j] = s[i * 4 + j];
        __syncthreads();

        // O += P @ V
        #pragma unroll 8
        for (int n = 0; n < FB_BN; ++n) {
            float pv[4], vv[4];
            #pragma unroll
            for (int i = 0; i < 4; ++i) pv[i] = Ps[(r0 + i) * FB_LD + n];
            #pragma unroll
            for (int j = 0; j < 4; ++j) vv[j] = Vs[n * FB_LD + c0 + j];
            #pragma unroll
            for (int i = 0; i < 4; ++i)
                #pragma unroll
                for (int j = 0; j < 4; ++j)
                    o[i * 4 + j] = fmaf(pv[i], vv[j], o[i * 4 + j]);
        }
    }

    // normalize and write: out[b, n, h*64 + d]
    #pragma unroll
    for (int i = 0; i < 4; ++i) {
        float inv = 1.f / lrow[i];
        int m = q0 + r0 + i;
        #pragma unroll
        for (int j = 0; j < 4; ++j)
            out[(size_t)(b * NN + m) * INNER + h * DHEAD + c0 + j] =
                o[i * 4 + j] * inv;
    }
}

// ---------------------------------------------------------------------------
// Launch
// ---------------------------------------------------------------------------
extern "C" void kernel_launch(void* const* d_in, const int* in_sizes, int n_in,
                              void* d_out, int out_size)
{
    const float* x      = (const float*)d_in[0];  // (8,1024,512)
    const float* w_qkv  = (const float*)d_in[1];  // (512,1536)
    const float* temp   = (const float*)d_in[2];  // scalar
    const float* w_out  = (const float*)d_in[3];  // (512,512)
    const float* b_out  = (const float*)d_in[4];  // (512,)
    float* out = (float*)d_out;                   // (8,1024,512)

    float* qkv_buf = nullptr;
    float* attn_buf = nullptr;
    cudaGetSymbolAddress((void**)&qkv_buf,  g_qkv);
    cudaGetSymbolAddress((void**)&attn_buf, g_attn);

    // 1) QKV projection: (8192x512) @ (512x1536)
    {
        dim3 grid(QKV_COLS / GM_BN, MTOT / GM_BM);
        sgemm_kernel<<<grid, 256>>>(x, w_qkv, nullptr, qkv_buf,
                                    MTOT, QKV_COLS, DIM);
    }

    // 2) Flash attention
    {
        const int smem = 4 * FB_BM * FB_LD * sizeof(float);  // 66560 B
        cudaFuncSetAttribute(flash_attn_kernel,
                             cudaFuncAttributeMaxDynamicSharedMemorySize, smem);
        dim3 grid(NN / FB_BM, HEADS, BB);
        flash_attn_kernel<<<grid, 256, smem>>>(qkv_buf, temp, attn_buf);
    }

    // 3) Output projection + bias: (8192x512) @ (512x512) + b
    {
        dim3 grid(DIM / GM_BN, MTOT / GM_BM);
        sgemm_kernel<<<grid, 256>>>(attn_buf, w_out, b_out, out,
                                    MTOT, DIM, DIM);
    }
}